// round 1
// baseline (speedup 1.0000x reference)
#include <cuda_runtime.h>
#include <cuda_bf16.h>

// ---------------------------------------------------------------------------
// Problem: y = EqualizedConv2d(stride=2, 3x3, 256->512, scale 1/48)( blur4x4(x) ) + bias
//   x:      [16,256,128,128] f32
//   weight: [512,256,3,3]    f32 (OIHW)
//   bias:   [512]            f32
//   blur_k: [4,4]            f32
//   out:    [16,512,64,64]   f32
//
// Strategy (round 1): blur -> im2col (tf32-rounded) -> tf32 mma.sync GEMM.
//   M = 16*64*64 = 65536, N = 512, K = 256*9 = 2304
// ---------------------------------------------------------------------------

#define NIMG   16
#define CIN    256
#define HIN    128
#define COUT   512
#define HB     129            // blurred spatial size
#define OH     64
#define OW     64
#define KDIM   2304           // 256*9
#define MDIM   65536          // 16*64*64  (== 1<<16)

// Scratch (allowed: __device__ globals, no runtime allocation)
__device__ float g_xb[(long)NIMG * CIN * HB * HB];        // 68,161,536 floats
__device__ float g_A[(long)KDIM * MDIM];                  // 150,994,944 floats (~604 MB)
__device__ float g_B[(long)KDIM * COUT];                  // 1,179,648 floats

__device__ __forceinline__ float tf32_round(float v) {
    unsigned o;
    asm("cvt.rna.tf32.f32 %0, %1;" : "=r"(o) : "f"(v));
    return __uint_as_float(o);
}

// ---------------------------------------------------------------------------
// Kernel 1: 4x4 FIR blur, pad 2 each side, 128x128 -> 129x129 per (n,c)
// xb[n,c,i,j] = sum_{u,v} bk[u,v] * x[n,c,i+u-2,j+v-2]   (OOB -> 0)
// ---------------------------------------------------------------------------
__global__ void blur_kernel(const float* __restrict__ x, const float* __restrict__ bk) {
    long idx = (long)blockIdx.x * 256 + threadIdx.x;
    const long total = (long)NIMG * CIN * HB * HB;
    if (idx >= total) return;
    int j  = (int)(idx % HB);
    long t = idx / HB;
    int i  = (int)(t % HB);
    int nc = (int)(t / HB);
    const float* xp = x + (long)nc * (HIN * HIN);
    float acc = 0.f;
#pragma unroll
    for (int u = 0; u < 4; ++u) {
        int r = i + u - 2;
        if ((unsigned)r < (unsigned)HIN) {
#pragma unroll
            for (int v = 0; v < 4; ++v) {
                int c = j + v - 2;
                if ((unsigned)c < (unsigned)HIN)
                    acc += bk[u * 4 + v] * xp[r * HIN + c];
            }
        }
    }
    g_xb[idx] = acc;
}

// ---------------------------------------------------------------------------
// Kernel 2: im2col into A[k][m] (K-major rows, M contiguous), tf32-rounded.
//   k = c*9 + kh*3 + kw ;  m = (n*64 + oh)*64 + ow
//   A[k][m] = xb[n, c, 2*oh+kh, 2*ow+kw]
// ---------------------------------------------------------------------------
__global__ void im2col_kernel() {
    long idx = (long)blockIdx.x * 256 + threadIdx.x;   // < KDIM*MDIM
    int m = (int)(idx & (MDIM - 1));
    int k = (int)(idx >> 16);
    int kw = k % 3; int t = k / 3; int kh = t % 3; int c = t / 3;
    int ow = m & 63, oh = (m >> 6) & 63, n = m >> 12;
    long xi = ((long)(n * CIN + c) * HB + (2 * oh + kh)) * HB + (2 * ow + kw);
    g_A[idx] = tf32_round(g_xb[xi]);
}

// ---------------------------------------------------------------------------
// Kernel 3: weight prep  B[k][oc] = weight[oc][k] * (1/48), tf32-rounded
// ---------------------------------------------------------------------------
__global__ void bprep_kernel(const float* __restrict__ w) {
    int idx = blockIdx.x * 256 + threadIdx.x;          // < COUT*KDIM
    int k  = idx % KDIM;
    int oc = idx / KDIM;
    float v = w[idx] * (1.0f / 48.0f);                 // fan_in = 2304, 1/sqrt = 1/48
    g_B[(long)k * COUT + oc] = tf32_round(v);
}

// ---------------------------------------------------------------------------
// Kernel 4: GEMM  D[M=65536, N=512] = A^T(65536x2304) * B(2304x512), + bias.
// Block tile 128x128, BK=16, 256 threads (8 warps, 4(M) x 2(N)),
// warp tile 32x64 -> per warp 2 m16-tiles x 8 n8-tiles of m16n8k8 tf32 MMA.
// ---------------------------------------------------------------------------
__global__ __launch_bounds__(256) void gemm_kernel(const float* __restrict__ bias,
                                                   float* __restrict__ out) {
    __shared__ float As[16][132];   // [k][m], padded
    __shared__ float Bs[16][132];   // [k][n], padded

    const int tid  = threadIdx.x;
    const int warp = tid >> 5;
    const int lane = tid & 31;
    const int g    = lane >> 2;     // group id (0..7)
    const int tg   = lane & 3;      // thread-in-group (0..3)
    const int wm   = (warp & 3) * 32;
    const int wn   = (warp >> 2) * 64;
    const long m0  = (long)blockIdx.x * 128;
    const int n0   = blockIdx.y * 128;

    // gmem staging assignment: float4 id f in [0,512): row=f>>5 (two halves), col4=f&31
    const int r0 = tid >> 5;             // 0..7 (and r0+8 for the second half)
    const int c0 = (tid & 31) << 2;      // 0..124

    float acc[2][8][4];
#pragma unroll
    for (int a = 0; a < 2; ++a)
#pragma unroll
        for (int b = 0; b < 8; ++b)
#pragma unroll
            for (int c = 0; c < 4; ++c) acc[a][b][c] = 0.f;

    const float* Agp = g_A + m0 + c0;
    const float* Bgp = g_B + n0 + c0;

    // prologue: chunk 0
    float4 na0 = *(const float4*)(Agp + ((long)r0 << 16));
    float4 na1 = *(const float4*)(Agp + ((long)(r0 + 8) << 16));
    float4 nb0 = *(const float4*)(Bgp + r0 * COUT);
    float4 nb1 = *(const float4*)(Bgp + (r0 + 8) * COUT);
    *(float4*)&As[r0][c0]     = na0;
    *(float4*)&As[r0 + 8][c0] = na1;
    *(float4*)&Bs[r0][c0]     = nb0;
    *(float4*)&Bs[r0 + 8][c0] = nb1;
    __syncthreads();

    const int NCHUNK = KDIM / 16;   // 144
    for (int kc = 0; kc < NCHUNK; ++kc) {
        if (kc < NCHUNK - 1) {
            const float* Ag2 = Agp + (((long)(kc + 1) * 16) << 16);
            const float* Bg2 = Bgp + (long)(kc + 1) * 16 * COUT;
            na0 = *(const float4*)(Ag2 + ((long)r0 << 16));
            na1 = *(const float4*)(Ag2 + ((long)(r0 + 8) << 16));
            nb0 = *(const float4*)(Bg2 + r0 * COUT);
            nb1 = *(const float4*)(Bg2 + (r0 + 8) * COUT);
        }
#pragma unroll
        for (int ks = 0; ks < 2; ++ks) {
            const int kb = ks * 8;
            unsigned a[2][4];
#pragma unroll
            for (int mi = 0; mi < 2; ++mi) {
                int r = wm + mi * 16 + g;
                a[mi][0] = __float_as_uint(As[kb + tg][r]);
                a[mi][1] = __float_as_uint(As[kb + tg][r + 8]);
                a[mi][2] = __float_as_uint(As[kb + tg + 4][r]);
                a[mi][3] = __float_as_uint(As[kb + tg + 4][r + 8]);
            }
#pragma unroll
            for (int ni = 0; ni < 8; ++ni) {
                unsigned b0 = __float_as_uint(Bs[kb + tg][wn + ni * 8 + g]);
                unsigned b1 = __float_as_uint(Bs[kb + tg + 4][wn + ni * 8 + g]);
#pragma unroll
                for (int mi = 0; mi < 2; ++mi) {
                    asm volatile(
                        "mma.sync.aligned.m16n8k8.row.col.f32.tf32.tf32.f32 "
                        "{%0,%1,%2,%3}, {%4,%5,%6,%7}, {%8,%9}, {%0,%1,%2,%3};\n"
                        : "+f"(acc[mi][ni][0]), "+f"(acc[mi][ni][1]),
                          "+f"(acc[mi][ni][2]), "+f"(acc[mi][ni][3])
                        : "r"(a[mi][0]), "r"(a[mi][1]), "r"(a[mi][2]), "r"(a[mi][3]),
                          "r"(b0), "r"(b1));
                }
            }
        }
        __syncthreads();
        if (kc < NCHUNK - 1) {
            *(float4*)&As[r0][c0]     = na0;
            *(float4*)&As[r0 + 8][c0] = na1;
            *(float4*)&Bs[r0][c0]     = nb0;
            *(float4*)&Bs[r0 + 8][c0] = nb1;
            __syncthreads();
        }
    }

    // epilogue: D[m][oc] -> out[n, oc, oh, ow] + bias[oc]
    // m = (n<<12) + oh*64 + ow ; out idx = ((n*512 + oc)<<12) + (m & 4095)
#pragma unroll
    for (int mi = 0; mi < 2; ++mi) {
        long m    = m0 + wm + mi * 16 + g;
        long nimg = m >> 12;
        long rem  = m & 4095;
#pragma unroll
        for (int ni = 0; ni < 8; ++ni) {
            int oc = n0 + wn + ni * 8 + tg * 2;
            float bv0 = bias[oc];
            float bv1 = bias[oc + 1];
            float* p = out + ((nimg * COUT + oc) << 12) + rem;
            p[0]    = acc[mi][ni][0] + bv0;   // (m,   oc)
            p[4096] = acc[mi][ni][1] + bv1;   // (m,   oc+1)
            p[8]    = acc[mi][ni][2] + bv0;   // (m+8, oc)
            p[4104] = acc[mi][ni][3] + bv1;   // (m+8, oc+1)
        }
    }
}

// ---------------------------------------------------------------------------
extern "C" void kernel_launch(void* const* d_in, const int* in_sizes, int n_in,
                              void* d_out, int out_size) {
    const float* x    = (const float*)d_in[0];
    const float* w    = (const float*)d_in[1];
    const float* bias = (const float*)d_in[2];
    const float* bk   = (const float*)d_in[3];
    float* out = (float*)d_out;
    (void)in_sizes; (void)n_in; (void)out_size;

    const long blur_total = (long)NIMG * CIN * HB * HB;          // 68,161,536
    blur_kernel<<<(unsigned)((blur_total + 255) / 256), 256>>>(x, bk);

    im2col_kernel<<<(unsigned)(((long)KDIM * MDIM) / 256), 256>>>();   // 589,824 blocks

    bprep_kernel<<<(COUT * KDIM) / 256, 256>>>(w);               // 4,608 blocks

    dim3 grid(MDIM / 128, COUT / 128);                           // (512, 4)
    gemm_kernel<<<grid, 256>>>(bias, out);
}

// round 5
// speedup vs baseline: 1.0890x; 1.0890x over previous
#include <cuda_runtime.h>
#include <cuda_bf16.h>

// ---------------------------------------------------------------------------
// y = EqualizedConv2d(stride=2, 3x3, 256->512, scale 1/48)( blur4x4(x) ) + bias
//   x:      [16,256,128,128] f32   weight: [512,256,3,3] f32   bias: [512] f32
//   blur_k: [4,4] f32              out:    [16,512,64,64] f32
//
// Round 2: separable blur (2 passes) -> fused im2col inside tf32 GEMM
//   (conflict-free smem, double-buffered), M=65536 N=512 K=2304.
// ---------------------------------------------------------------------------

#define NIMG   16
#define CIN    256
#define HIN    128
#define COUT   512
#define HB     129
#define KDIM   2304
#define MDIM   65536

// Scratch
__device__ float g_xh[(long)NIMG * CIN * HIN * HB];   // 67,633,152 floats (H-blurred)
__device__ float g_xb[(long)NIMG * CIN * HB * HB];    // 68,161,536 floats (blurred)
__device__ float g_B [(long)KDIM * COUT];             // 1,179,648 floats
__device__ float g_k [4];                             // separable 1-D taps

__device__ __forceinline__ float tf32_round(float v) {
    unsigned o;
    asm("cvt.rna.tf32.f32 %0, %1;" : "=r"(o) : "f"(v));
    return __uint_as_float(o);
}

// ---------------------------------------------------------------------------
// Kernel 0: recover 1-D taps. K = outer(k,k) with sum(k)=1, so k[t] = row-sum.
// All values are dyadic rationals -> exact in f32.
// ---------------------------------------------------------------------------
__global__ void prep_k_kernel(const float* __restrict__ bk) {
    if (threadIdx.x < 4) {
        int t = threadIdx.x;
        g_k[t] = bk[t*4+0] + bk[t*4+1] + bk[t*4+2] + bk[t*4+3];
    }
}

// ---------------------------------------------------------------------------
// Kernel 1a: horizontal 4-tap, pad 2/1:  xh[nc, i, j] , i in [0,128), j in [0,129)
// ---------------------------------------------------------------------------
__global__ void blur_h_kernel(const float* __restrict__ x) {
    long idx = (long)blockIdx.x * 256 + threadIdx.x;
    const long total = (long)NIMG * CIN * HIN * HB;
    if (idx >= total) return;
    int j  = (int)(idx % HB);
    long t = idx / HB;
    int i  = (int)(t % HIN);
    long nc = t / HIN;
    const float* xp = x + (nc * HIN + i) * HIN;
    float k0 = g_k[0], k1 = g_k[1], k2 = g_k[2], k3 = g_k[3];
    float acc = 0.f;
    int c = j - 2;
    if ((unsigned)(c    ) < HIN) acc += k0 * xp[c];
    if ((unsigned)(c + 1) < HIN) acc += k1 * xp[c + 1];
    if ((unsigned)(c + 2) < HIN) acc += k2 * xp[c + 2];
    if ((unsigned)(c + 3) < HIN) acc += k3 * xp[c + 3];
    g_xh[idx] = acc;
}

// ---------------------------------------------------------------------------
// Kernel 1b: vertical 4-tap: xb[nc, i, j], i,j in [0,129)
// ---------------------------------------------------------------------------
__global__ void blur_v_kernel() {
    long idx = (long)blockIdx.x * 256 + threadIdx.x;
    const long total = (long)NIMG * CIN * HB * HB;
    if (idx >= total) return;
    int j  = (int)(idx % HB);
    long t = idx / HB;
    int i  = (int)(t % HB);
    long nc = t / HB;
    const float* hp = g_xh + nc * (HIN * HB) + j;
    float k0 = g_k[0], k1 = g_k[1], k2 = g_k[2], k3 = g_k[3];
    float acc = 0.f;
    int r = i - 2;
    if ((unsigned)(r    ) < HIN) acc += k0 * hp[(r    ) * HB];
    if ((unsigned)(r + 1) < HIN) acc += k1 * hp[(r + 1) * HB];
    if ((unsigned)(r + 2) < HIN) acc += k2 * hp[(r + 2) * HB];
    if ((unsigned)(r + 3) < HIN) acc += k3 * hp[(r + 3) * HB];
    g_xb[idx] = acc;
}

// ---------------------------------------------------------------------------
// Kernel 2: weight prep  B[k][oc] = weight[oc][k] * (1/48), tf32-rounded
// ---------------------------------------------------------------------------
__global__ void bprep_kernel(const float* __restrict__ w) {
    int idx = blockIdx.x * 256 + threadIdx.x;          // < COUT*KDIM
    int k  = idx % KDIM;
    int oc = idx / KDIM;
    g_B[(long)k * COUT + oc] = tf32_round(w[idx] * (1.0f / 48.0f));
}

// ---------------------------------------------------------------------------
// Kernel 3: fused im2col + GEMM.
//   D[M,N] = A^T * B,  A[k][m] = xb[n, c, 2*oh+kh, 2*ow+kw] (built on the fly)
// Block 128x128, BK=16, 256 thr, 8 warps (4M x 2N), warp 32x64 of m16n8k8 tf32.
// Smem double-buffered, row stride 136 (mod 32 == 8 -> conflict-free frags).
// ---------------------------------------------------------------------------
#define LDP 136

__global__ __launch_bounds__(256) void gemm_kernel(const float* __restrict__ bias,
                                                   float* __restrict__ out) {
    __shared__ float As[2][16][LDP];
    __shared__ float Bs[2][16][LDP];

    const int tid  = threadIdx.x;
    const int warp = tid >> 5;
    const int lane = tid & 31;
    const int g    = lane >> 2;
    const int tg   = lane & 3;
    const int wm   = (warp & 3) * 32;
    const int wn   = (warp >> 2) * 64;
    const int n0   = blockIdx.x * 128;            // N-tile (fast dim: A reuse in L2)
    const long m0  = (long)blockIdx.y * 128;      // M-tile

    // staging assignment
    const int r0 = tid >> 5;                      // k-row 0..7 (and +8)
    const int c0 = (tid & 31) << 2;               // m/n offset 0..124

    // fused-im2col base address for this thread's 4 m-positions (m = m0+c0+j)
    const int n_img = (int)(m0 >> 12);
    const int oh    = (int)((m0 >> 6) & 63) + (c0 >> 6);
    const int owb   = c0 & 63;
    const long abase = (((long)n_img * CIN) * HB + 2 * oh) * HB + 2 * owb;

    float acc[2][8][4];
#pragma unroll
    for (int a = 0; a < 2; ++a)
#pragma unroll
        for (int b = 0; b < 8; ++b)
#pragma unroll
            for (int c = 0; c < 4; ++c) acc[a][b][c] = 0.f;

    const float* Bgp = g_B + n0 + c0;

    float  ra0[4], ra1[4];
    float4 rb0, rb1;

    // ---- staging helpers (macros keep everything in registers) ----
#define LOAD_CHUNK(KC)                                                         \
    {                                                                          \
        int k_ = (KC) * 16 + r0;                                               \
        int c_ = k_ / 9, rem_ = k_ - 9 * c_;                                   \
        int kh_ = rem_ / 3, kw_ = rem_ - 3 * kh_;                              \
        long off_ = abase + (long)c_ * (HB * HB) + kh_ * HB + kw_;             \
        ra0[0] = g_xb[off_];     ra0[1] = g_xb[off_ + 2];                      \
        ra0[2] = g_xb[off_ + 4]; ra0[3] = g_xb[off_ + 6];                      \
        k_ += 8;                                                               \
        c_ = k_ / 9; rem_ = k_ - 9 * c_;                                       \
        kh_ = rem_ / 3; kw_ = rem_ - 3 * kh_;                                  \
        off_ = abase + (long)c_ * (HB * HB) + kh_ * HB + kw_;                  \
        ra1[0] = g_xb[off_];     ra1[1] = g_xb[off_ + 2];                      \
        ra1[2] = g_xb[off_ + 4]; ra1[3] = g_xb[off_ + 6];                      \
        const float* bp_ = Bgp + (long)((KC) * 16) * COUT;                     \
        rb0 = *(const float4*)(bp_ + r0 * COUT);                               \
        rb1 = *(const float4*)(bp_ + (r0 + 8) * COUT);                         \
    }

#define STORE_CHUNK(S)                                                         \
    {                                                                          \
        float4 t0_ = make_float4(tf32_round(ra0[0]), tf32_round(ra0[1]),       \
                                 tf32_round(ra0[2]), tf32_round(ra0[3]));      \
        float4 t1_ = make_float4(tf32_round(ra1[0]), tf32_round(ra1[1]),       \
                                 tf32_round(ra1[2]), tf32_round(ra1[3]));      \
        *(float4*)&As[S][r0][c0]     = t0_;                                    \
        *(float4*)&As[S][r0 + 8][c0] = t1_;                                    \
        *(float4*)&Bs[S][r0][c0]     = rb0;                                    \
        *(float4*)&Bs[S][r0 + 8][c0] = rb1;                                    \
    }

    LOAD_CHUNK(0);
    STORE_CHUNK(0);
    __syncthreads();

    const int NCHUNK = KDIM / 16;   // 144
    for (int kc = 0; kc < NCHUNK; ++kc) {
        const int s = kc & 1;
        if (kc + 1 < NCHUNK) LOAD_CHUNK(kc + 1);

#pragma unroll
        for (int ks = 0; ks < 2; ++ks) {
            const int kb = ks * 8;
            unsigned a[2][4];
#pragma unroll
            for (int mi = 0; mi < 2; ++mi) {
                int r = wm + mi * 16 + g;
                a[mi][0] = __float_as_uint(As[s][kb + tg][r]);
                a[mi][1] = __float_as_uint(As[s][kb + tg][r + 8]);
                a[mi][2] = __float_as_uint(As[s][kb + tg + 4][r]);
                a[mi][3] = __float_as_uint(As[s][kb + tg + 4][r + 8]);
            }
#pragma unroll
            for (int ni = 0; ni < 8; ++ni) {
                unsigned b0 = __float_as_uint(Bs[s][kb + tg][wn + ni * 8 + g]);
                unsigned b1 = __float_as_uint(Bs[s][kb + tg + 4][wn + ni * 8 + g]);
#pragma unroll
                for (int mi = 0; mi < 2; ++mi) {
                    asm volatile(
                        "mma.sync.aligned.m16n8k8.row.col.f32.tf32.tf32.f32 "
                        "{%0,%1,%2,%3}, {%4,%5,%6,%7}, {%8,%9}, {%0,%1,%2,%3};\n"
                        : "+f"(acc[mi][ni][0]), "+f"(acc[mi][ni][1]),
                          "+f"(acc[mi][ni][2]), "+f"(acc[mi][ni][3])
                        : "r"(a[mi][0]), "r"(a[mi][1]), "r"(a[mi][2]), "r"(a[mi][3]),
                          "r"(b0), "r"(b1));
                }
            }
        }

        if (kc + 1 < NCHUNK) STORE_CHUNK(s ^ 1);
        __syncthreads();
    }

    // epilogue: D[m][oc] -> out[n, oc, oh, ow] + bias[oc]
#pragma unroll
    for (int mi = 0; mi < 2; ++mi) {
        long m    = m0 + wm + mi * 16 + g;
        long nimg = m >> 12;
        long rem  = m & 4095;
#pragma unroll
        for (int ni = 0; ni < 8; ++ni) {
            int oc = n0 + wn + ni * 8 + tg * 2;
            float bv0 = bias[oc];
            float bv1 = bias[oc + 1];
            float* p = out + ((nimg * COUT + oc) << 12) + rem;
            p[0]    = acc[mi][ni][0] + bv0;
            p[4096] = acc[mi][ni][1] + bv1;
            p[8]    = acc[mi][ni][2] + bv0;
            p[4104] = acc[mi][ni][3] + bv1;
        }
    }
#undef LOAD_CHUNK
#undef STORE_CHUNK
}

// ---------------------------------------------------------------------------
extern "C" void kernel_launch(void* const* d_in, const int* in_sizes, int n_in,
                              void* d_out, int out_size) {
    const float* x    = (const float*)d_in[0];
    const float* w    = (const float*)d_in[1];
    const float* bias = (const float*)d_in[2];
    const float* bk   = (const float*)d_in[3];
    float* out = (float*)d_out;
    (void)in_sizes; (void)n_in; (void)out_size;

    prep_k_kernel<<<1, 32>>>(bk);

    const long nh = (long)NIMG * CIN * HIN * HB;   // 67,633,152
    blur_h_kernel<<<(unsigned)((nh + 255) / 256), 256>>>(x);

    const long nv = (long)NIMG * CIN * HB * HB;    // 68,161,536
    blur_v_kernel<<<(unsigned)((nv + 255) / 256), 256>>>();

    bprep_kernel<<<(COUT * KDIM) / 256, 256>>>(w);

    dim3 grid(COUT / 128, MDIM / 128);             // (4, 512): N fast -> A L2 reuse
    gemm_kernel<<<grid, 256>>>(bias, out);
}

// round 9
// speedup vs baseline: 1.4025x; 1.2879x over previous
#include <cuda_runtime.h>
#include <cstdint>

// ---------------------------------------------------------------------------
// y = EqualizedConv2d(stride=2, 3x3, 256->512, 1/48)( blur4x4(x) ) + bias
// Round 7: fused separable blur (phase-split, tf32-pre-rounded) ->
//          tf32 mma.sync GEMM with fragment-packed smem (LDS.128 frags),
//          block 256x128, warp 64x64, double-buffered.
//   M=65536, N=512, K=2304.
// ---------------------------------------------------------------------------

#define NIMG   16
#define CIN    256
#define HIN    128
#define COUT   512
#define KDIM   2304
#define MDIM   65536
#define HPW    68                 // padded phase row width (65 valid)
#define CROW   4420               // 65*68 floats per (nc, phase)
#define NBLK2  1131520            // 256*CROW (per image within phase)
#define PHBLK  18104320           // 16*NBLK2 (per phase)
#define NCHUNK 144                // K / 16

// Scratch (__device__ globals only)
__device__ float g_xp[(size_t)4 * PHBLK];       // phase-split blurred, tf32-rounded
__device__ float g_Bp[(size_t)KDIM * COUT];     // fragment-packed weights
__device__ int   g_P[KDIM];                     // per-k phase offsets
__device__ float g_k[4];                        // separable 1-D taps

__device__ __forceinline__ float tf32_round(float v) {
    unsigned o;
    asm("cvt.rna.tf32.f32 %0, %1;" : "=r"(o) : "f"(v));
    return __uint_as_float(o);
}

// ---------------------------------------------------------------------------
// Kernel 0a: 1-D taps (row sums of the normalized outer-product kernel; exact)
// ---------------------------------------------------------------------------
__global__ void prep_k_kernel(const float* __restrict__ bk) {
    if (threadIdx.x < 4) {
        int t = threadIdx.x;
        g_k[t] = bk[t*4+0] + bk[t*4+1] + bk[t*4+2] + bk[t*4+3];
    }
}

// Kernel 0b: per-k phase offsets.  k = c*9 + kh*3 + kw
__global__ void prep_P_kernel() {
    int k = blockIdx.x * 256 + threadIdx.x;
    if (k >= KDIM) return;
    int c  = k / 9, rem = k - 9 * c;
    int kh = rem / 3, kw = rem - 3 * kh;
    int ph = (kh & 1) * 2 + (kw & 1);
    g_P[k] = ph * PHBLK + c * CROW + (kh >> 1) * HPW + (kw >> 1);
}

// ---------------------------------------------------------------------------
// Kernel 1: fused separable 4x4 blur. CTA = (nc, quarter). Output rows per
// quarter: {33,32,32,32}. Writes phase-split layout, tf32-rounded.
// ---------------------------------------------------------------------------
__global__ void __launch_bounds__(256) blur_kernel(const float* __restrict__ x) {
    __shared__ float xs[35 * 128];
    __shared__ float hs[35 * 132];

    const int nc  = blockIdx.x;
    const int q   = blockIdx.y;
    const int tid = threadIdx.x;

    const int i0   = (q == 0) ? 0 : (q == 1) ? 33 : (q == 2) ? 65 : 97;
    const int icnt = (q == 0) ? 33 : 32;
    int in_lo = i0 - 2;          if (in_lo < 0)   in_lo = 0;
    int in_hi = i0 + icnt + 1;   if (in_hi > 128) in_hi = 128;
    const int nrows = in_hi - in_lo;

    const float k0 = g_k[0], k1 = g_k[1], k2 = g_k[2], k3 = g_k[3];

    // load rows [in_lo, in_hi) of this nc image (contiguous)
    {
        const float4* src = (const float4*)(x + ((size_t)nc * HIN + in_lo) * HIN);
        float4* dst = (float4*)xs;
        for (int t = tid; t < nrows * 32; t += 256) dst[t] = src[t];
    }
    __syncthreads();

    // horizontal 4-tap: hs[rr][j], j in [0,129)
    for (int t = tid; t < nrows * 129; t += 256) {
        int j = t % 129, rr = t / 129;
        const float* xr = xs + rr * 128;
        float acc = 0.f;
        int c = j - 2;
        if ((unsigned)(c    ) < 128u) acc += k0 * xr[c];
        if ((unsigned)(c + 1) < 128u) acc += k1 * xr[c + 1];
        if ((unsigned)(c + 2) < 128u) acc += k2 * xr[c + 2];
        if ((unsigned)(c + 3) < 128u) acc += k3 * xr[c + 3];
        hs[rr * 132 + j] = acc;
    }
    __syncthreads();

    // vertical 4-tap + phase-split write (tf32-rounded)
    const int base_nc = nc * CROW;
    for (int t = tid; t < icnt * 129; t += 256) {
        int j = t % 129, io = t / 129;
        int i = i0 + io;
        int r = i - 2;
        float acc = 0.f;
        if ((unsigned)(r    ) < 128u) acc += k0 * hs[(r     - in_lo) * 132 + j];
        if ((unsigned)(r + 1) < 128u) acc += k1 * hs[(r + 1 - in_lo) * 132 + j];
        if ((unsigned)(r + 2) < 128u) acc += k2 * hs[(r + 2 - in_lo) * 132 + j];
        if ((unsigned)(r + 3) < 128u) acc += k3 * hs[(r + 3 - in_lo) * 132 + j];
        int ph = (i & 1) * 2 + (j & 1);
        g_xp[ph * PHBLK + base_nc + (i >> 1) * HPW + (j >> 1)] = tf32_round(acc);
    }
}

// ---------------------------------------------------------------------------
// Kernel 2: weights -> fragment-packed, scaled, tf32-rounded.
// slot8 idx = (((nt*144 + ck)*2 + ks)*16 + nt8)*32 + lane ; holds
// { B[k][n], B[k+4][n] } with k = ck*16+ks*8+(lane&3), n = nt*128+nt8*8+(lane>>2)
// ---------------------------------------------------------------------------
__global__ void bprep_kernel(const float* __restrict__ w) {
    int idx = blockIdx.x * 256 + threadIdx.x;          // < 589824
    int lane = idx & 31;
    int nt8  = (idx >> 5) & 15;
    int ks   = (idx >> 9) & 1;
    int rest = idx >> 10;
    int ck   = rest % NCHUNK;
    int nt   = rest / NCHUNK;
    int n = nt * 128 + nt8 * 8 + (lane >> 2);
    int k = ck * 16 + ks * 8 + (lane & 3);
    const float s = 1.0f / 48.0f;
    float2 v;
    v.x = tf32_round(w[(size_t)n * KDIM + k]     * s);
    v.y = tf32_round(w[(size_t)n * KDIM + k + 4] * s);
    ((float2*)g_Bp)[idx] = v;
}

// ---------------------------------------------------------------------------
// Kernel 3: tf32 GEMM, fused im2col A-gather, fragment-packed smem.
// Block 256(M) x 128(N), BK=16, 8 warps (4M x 2N), warp 64x64.
// As[s]: 32 combos (ks*16+mt) x 32 lanes x 4 floats (LDS.128 frags)
// Bs[s]: 32 combos (ks*16+nt8) x 32 lanes x 2 floats (LDS.64 frags)
// ---------------------------------------------------------------------------
__global__ void __launch_bounds__(256, 1)
gemm_kernel(const float* __restrict__ bias, float* __restrict__ out) {
    __shared__ float As[2][4096];   // 32 KB
    __shared__ float Bs[2][2048];   // 16 KB   (total 48 KB exactly)

    const int tid   = threadIdx.x;
    const int warp  = tid >> 5;
    const int lane  = tid & 31;
    const int g     = lane >> 2;
    const int tg    = lane & 3;
    const int warpm = warp & 3;
    const int warpn = warp >> 2;
    const int n0    = blockIdx.x << 7;
    const int m0    = blockIdx.y << 8;

    // staging: this thread owns combos {warp, warp+8, warp+16, warp+24}
    // precompute im2col bases (chunk-invariant): ab[j][h] for m = m0+mt*16+g+8h
    int ab[4][2];
#pragma unroll
    for (int j = 0; j < 4; ++j) {
        int mt = (warp + 8 * j) & 15;
#pragma unroll
        for (int h = 0; h < 2; ++h) {
            int m = m0 + mt * 16 + g + 8 * h;
            ab[j][h] = (m >> 12) * NBLK2 + ((m >> 6) & 63) * HPW + (m & 63);
        }
    }
    const float4* Bg = (const float4*)g_Bp + (size_t)(blockIdx.x * NCHUNK) * 512;

    float acc[4][8][4];
#pragma unroll
    for (int a = 0; a < 4; ++a)
#pragma unroll
        for (int b = 0; b < 8; ++b)
#pragma unroll
            for (int c = 0; c < 4; ++c) acc[a][b][c] = 0.f;

    float  va[4][4];
    float4 vb0, vb1;

    auto prefetch = [&](int kc) {
        int kb = kc * 16 + tg;
        int p0 = g_P[kb], p1 = g_P[kb + 4], p2 = g_P[kb + 8], p3 = g_P[kb + 12];
#pragma unroll
        for (int j = 0; j < 4; ++j) {
            int ks = (warp + 8 * j) >> 4;        // 0 for j=0,1 ; 1 for j=2,3
            int q0 = ks ? p2 : p0;
            int q1 = ks ? p3 : p1;
            va[j][0] = g_xp[ab[j][0] + q0];
            va[j][1] = g_xp[ab[j][1] + q0];
            va[j][2] = g_xp[ab[j][0] + q1];
            va[j][3] = g_xp[ab[j][1] + q1];
        }
        const float4* src = Bg + (size_t)kc * 512;
        vb0 = src[tid];
        vb1 = src[tid + 256];
    };
    auto store_stage = [&](int sb) {
#pragma unroll
        for (int j = 0; j < 4; ++j) {
            int combo = warp + 8 * j;
            *(float4*)&As[sb][(combo * 32 + lane) * 4] =
                make_float4(va[j][0], va[j][1], va[j][2], va[j][3]);
        }
        ((float4*)Bs[sb])[tid]       = vb0;
        ((float4*)Bs[sb])[tid + 256] = vb1;
    };

    prefetch(0);
    store_stage(0);
    __syncthreads();

    for (int kc = 0; kc < NCHUNK; ++kc) {
        const int s = kc & 1;
        if (kc + 1 < NCHUNK) prefetch(kc + 1);

#pragma unroll
        for (int ks = 0; ks < 2; ++ks) {
            float4 fa[4];
#pragma unroll
            for (int mi = 0; mi < 4; ++mi)
                fa[mi] = *(const float4*)
                    &As[s][(((ks << 4) + (warpm << 2) + mi) * 32 + lane) << 2];
#pragma unroll
            for (int ni = 0; ni < 8; ++ni) {
                float2 fb = *(const float2*)
                    &Bs[s][((((ks << 4) + (warpn << 3) + ni) * 32) + lane) << 1];
                unsigned b0 = __float_as_uint(fb.x);
                unsigned b1 = __float_as_uint(fb.y);
#pragma unroll
                for (int mi = 0; mi < 4; ++mi) {
                    asm volatile(
                        "mma.sync.aligned.m16n8k8.row.col.f32.tf32.tf32.f32 "
                        "{%0,%1,%2,%3}, {%4,%5,%6,%7}, {%8,%9}, {%0,%1,%2,%3};\n"
                        : "+f"(acc[mi][ni][0]), "+f"(acc[mi][ni][1]),
                          "+f"(acc[mi][ni][2]), "+f"(acc[mi][ni][3])
                        : "r"(__float_as_uint(fa[mi].x)), "r"(__float_as_uint(fa[mi].y)),
                          "r"(__float_as_uint(fa[mi].z)), "r"(__float_as_uint(fa[mi].w)),
                          "r"(b0), "r"(b1));
                }
            }
        }

        if (kc + 1 < NCHUNK) store_stage(s ^ 1);
        __syncthreads();
    }

    // epilogue: D[m][oc] -> out[n, oc, oh, ow] + bias
#pragma unroll
    for (int ni = 0; ni < 8; ++ni) {
        int oc = n0 + (warpn << 6) + (ni << 3) + (tg << 1);
        float bv0 = __ldg(&bias[oc]);
        float bv1 = __ldg(&bias[oc + 1]);
#pragma unroll
        for (int mi = 0; mi < 4; ++mi) {
            int m = m0 + (warpm << 6) + (mi << 4) + g;
            float* p = out + (((size_t)(m >> 12) * COUT + oc) << 12) + (m & 4095);
            p[0]    = acc[mi][ni][0] + bv0;   // (m,   oc)
            p[4096] = acc[mi][ni][1] + bv1;   // (m,   oc+1)
            p[8]    = acc[mi][ni][2] + bv0;   // (m+8, oc)
            p[4104] = acc[mi][ni][3] + bv1;   // (m+8, oc+1)
        }
    }
}

// ---------------------------------------------------------------------------
extern "C" void kernel_launch(void* const* d_in, const int* in_sizes, int n_in,
                              void* d_out, int out_size) {
    const float* x    = (const float*)d_in[0];
    const float* w    = (const float*)d_in[1];
    const float* bias = (const float*)d_in[2];
    const float* bk   = (const float*)d_in[3];
    float* out = (float*)d_out;
    (void)in_sizes; (void)n_in; (void)out_size;

    prep_k_kernel<<<1, 32>>>(bk);
    prep_P_kernel<<<(KDIM + 255) / 256, 256>>>();

    blur_kernel<<<dim3(NIMG * CIN, 4), 256>>>(x);

    bprep_kernel<<<(COUT * KDIM / 2) / 256, 256>>>(w);

    dim3 grid(COUT / 128, MDIM / 256);      // (4, 256): n fast -> A-tile L2 reuse
    gemm_kernel<<<grid, 256>>>(bias, out);
}